// round 8
// baseline (speedup 1.0000x reference)
#include <cuda_runtime.h>
#include <cuda_fp16.h>
#include <cstdint>
#include <math.h>

#define RES 7
#define SAMP 14
#define C_CH 256
#define B_SZ 4
#define N_ROI 512
#define M_TOT 2048
#define K1 12544
#define FC 1024
#define OUT_D 100

// ======================= scratch =======================
__device__ float g_f0[(size_t)B_SZ * 128 * 128 * C_CH];
__device__ float g_f1[(size_t)B_SZ * 64 * 64 * C_CH];
__device__ float g_f2[(size_t)B_SZ * 32 * 32 * C_CH];
__device__ __half g_Xhi[(size_t)M_TOT * K1];
__device__ __half g_Xlo[(size_t)M_TOT * K1];
__device__ __half g_W1hi[(size_t)K1 * FC];   // [K][N] native layout
__device__ __half g_W1lo[(size_t)K1 * FC];
__device__ __half g_W2hi[(size_t)FC * FC];
__device__ __half g_W2lo[(size_t)FC * FC];
__device__ __half g_A2hi[(size_t)M_TOT * FC];
__device__ __half g_A2lo[(size_t)M_TOT * FC];
__device__ float g_Y1[(size_t)M_TOT * FC];
__device__ float g_Y2[(size_t)M_TOT * FC];
__device__ float g_mu[FC];
__device__ float g_var[FC];

// ======================= small PTX helpers =======================
__device__ __forceinline__ uint32_t smem_u32(const void* p) {
    uint32_t a;
    asm("{ .reg .u64 t; cvta.to.shared.u64 t, %1; cvt.u32.u64 %0, t; }" : "=r"(a) : "l"(p));
    return a;
}
__device__ __forceinline__ void cp_async16(uint32_t dst, const void* src) {
    asm volatile("cp.async.cg.shared.global [%0], [%1], 16;" :: "r"(dst), "l"(src));
}
__device__ __forceinline__ void cp_commit() { asm volatile("cp.async.commit_group;"); }
template <int N> __device__ __forceinline__ void cp_wait() {
    asm volatile("cp.async.wait_group %0;" :: "n"(N));
}
__device__ __forceinline__ void ldsm_x4(uint32_t r[4], uint32_t addr) {
    asm volatile("ldmatrix.sync.aligned.m8n8.x4.shared.b16 {%0,%1,%2,%3}, [%4];"
                 : "=r"(r[0]), "=r"(r[1]), "=r"(r[2]), "=r"(r[3]) : "r"(addr));
}
__device__ __forceinline__ void ldsm_x4_t(uint32_t r[4], uint32_t addr) {
    asm volatile("ldmatrix.sync.aligned.m8n8.x4.trans.shared.b16 {%0,%1,%2,%3}, [%4];"
                 : "=r"(r[0]), "=r"(r[1]), "=r"(r[2]), "=r"(r[3]) : "r"(addr));
}
__device__ __forceinline__ void mma16816(float c[4], const uint32_t a[4], const uint32_t b[2]) {
    asm volatile("mma.sync.aligned.m16n8k16.row.col.f32.f16.f16.f32 "
                 "{%0,%1,%2,%3}, {%4,%5,%6,%7}, {%8,%9}, {%0,%1,%2,%3};"
                 : "+f"(c[0]), "+f"(c[1]), "+f"(c[2]), "+f"(c[3])
                 : "r"(a[0]), "r"(a[1]), "r"(a[2]), "r"(a[3]), "r"(b[0]), "r"(b[1]));
}

// ======================= NCHW -> NHWC =======================
__global__ void transpose_nchw_nhwc(const float* __restrict__ in,
                                    float* __restrict__ out, int HW) {
    __shared__ float tile[32][33];
    int b  = blockIdx.z;
    int s0 = blockIdx.x * 32;
    int c0 = blockIdx.y * 32;
    int tx = threadIdx.x, ty = threadIdx.y;
    const float* inb = in + (size_t)b * C_CH * HW;
    float* outb = out + (size_t)b * HW * C_CH;
#pragma unroll
    for (int i = 0; i < 32; i += 8)
        tile[ty + i][tx] = inb[(size_t)(c0 + ty + i) * HW + s0 + tx];
    __syncthreads();
#pragma unroll
    for (int i = 0; i < 32; i += 8)
        outb[(size_t)(s0 + ty + i) * C_CH + c0 + tx] = tile[tx][ty + i];
}

// ======================= W fp32 -> hi/lo fp16 (same layout) =======================
__global__ void split_w(const float* __restrict__ in, __half* __restrict__ hi,
                        __half* __restrict__ lo, int total) {
    int idx = blockIdx.x * blockDim.x + threadIdx.x;
    if (idx >= total) return;
    float v = in[idx];
    __half h = __float2half_rn(v);
    hi[idx] = h;
    lo[idx] = __float2half_rn(v - __half2float(h));
}

// ======================= ROI align -> X hi/lo fp16 =======================
__global__ void roi_align_kernel(const float* __restrict__ bbox2d,
                                 const int* __restrict__ anchor) {
    int roi = blockIdx.x;
    int b   = roi / N_ROI;
    int tid = threadIdx.x;

    __shared__ int   sp0[2][SAMP], sp1[2][SAMP];
    __shared__ float sl [2][SAMP], sv [2][SAMP];

    int level = anchor[roi] / 3;
    float scale = (level == 0) ? 0.25f : (level == 1) ? 0.125f : 0.0625f;
    int   H     = (level == 0) ? 128   : (level == 1) ? 64     : 32;
    const float* F = (level == 0) ? g_f0 : (level == 1) ? g_f1 : g_f2;
    F += b * H * H * C_CH;

    float cy = bbox2d[roi*4+0], cx = bbox2d[roi*4+1];
    float hh = bbox2d[roi*4+2], ww = bbox2d[roi*4+3];
    float t = cy - 0.5f*hh, l = cx - 0.5f*ww;
    float bo = cy + 0.5f*hh, r = cx + 0.5f*ww;

    if (tid < 2 * SAMP) {
        int axis = tid / SAMP;
        int j    = tid % SAMP;
        float start = ((axis == 0) ? t : l) * scale - 0.5f;
        float bs    = ((axis == 0) ? (bo - t) : (r - l)) * scale / (float)RES;
        float g     = ((float)j + 0.5f) * 0.5f;
        float pos   = start + g * bs;
        float valid = (pos > -1.0f && pos < (float)H) ? 1.0f : 0.0f;
        float p  = fminf(fmaxf(pos, 0.0f), (float)(H - 1));
        int  p0  = (int)floorf(p);
        int  p1  = min(p0 + 1, H - 1);
        sp0[axis][j] = p0;  sp1[axis][j] = p1;
        sl [axis][j] = p - (float)p0;
        sv [axis][j] = valid;
    }
    __syncthreads();

    int c = tid;
    int xbase = roi * K1 + c * 49;

#pragma unroll
    for (int py = 0; py < 7; py++) {
#pragma unroll
        for (int px = 0; px < 7; px++) {
            float v = 0.f;
#pragma unroll
            for (int sy = 0; sy < 2; sy++) {
                int j = py * 2 + sy;
                int y0 = sp0[0][j], y1 = sp1[0][j];
                float ly = sl[0][j], vy = sv[0][j];
                float hy = 1.f - ly;
#pragma unroll
                for (int sx = 0; sx < 2; sx++) {
                    int i = px * 2 + sx;
                    int x0 = sp0[1][i], x1 = sp1[1][i];
                    float lx = sl[1][i], vx = sv[1][i];
                    float hx = 1.f - lx;
                    float f00 = F[(y0 * H + x0) * C_CH + c];
                    float f01 = F[(y0 * H + x1) * C_CH + c];
                    float f10 = F[(y1 * H + x0) * C_CH + c];
                    float f11 = F[(y1 * H + x1) * C_CH + c];
                    v += (vy * vx) * (f00 * hy * hx + f01 * hy * lx +
                                      f10 * ly * hx + f11 * ly * lx);
                }
            }
            v *= 0.25f;
            __half h = __float2half_rn(v);
            g_Xhi[xbase + py * 7 + px] = h;
            g_Xlo[xbase + py * 7 + px] = __float2half_rn(v - __half2float(h));
        }
    }
}

// ======================= fp16-split HMMA GEMM =======================
// C[M,N] = (Ahi+Alo)[M,K] @ (Whi+Wlo)[K,N] + bias, fp32 out.
// CTA 128x128, BK=32, 8 warps (2x4), warp tile 64x32, 3-stage cp.async.
#define SA_STRIDE 80            // 32 halves (64B) + 16B pad
#define SB_STRIDE 272          // 128 halves (256B) + 16B pad
#define A_TILE (128 * SA_STRIDE)    // 10240
#define B_TILE (32 * SB_STRIDE)     // 8704
#define STAGE_BYTES (2 * A_TILE + 2 * B_TILE)   // 37888
#define N_STAGE 3
#define GEMM_SMEM (N_STAGE * STAGE_BYTES)

__global__ void __launch_bounds__(256)
gemm_split_f16(const __half* __restrict__ Ahi, const __half* __restrict__ Alo,
               const __half* __restrict__ Whi, const __half* __restrict__ Wlo,
               const float* __restrict__ bias, float* __restrict__ Cc,
               int N, int K) {
    extern __shared__ char smem[];
    uint32_t sb = smem_u32(smem);
    int tid = threadIdx.x, wid = tid >> 5, lid = tid & 31;
    int mBase = blockIdx.y * 128, nBase = blockIdx.x * 128;
    int wm = wid >> 2, wn = wid & 3;      // 2 x 4 warp grid

    float acc[4][4][4];
#pragma unroll
    for (int i = 0; i < 4; i++)
#pragma unroll
        for (int j = 0; j < 4; j++)
#pragma unroll
            for (int q = 0; q < 4; q++) acc[i][j][q] = 0.f;

    const int nIter = K >> 5;   // BK = 32

    // ---- stage loader: 8 cp.async(16B) per thread ----
    auto load_stage = [&](int iter, int stage) {
        int k0 = iter * 32;
        uint32_t stBase = sb + stage * STAGE_BYTES;
#pragma unroll
        for (int i = 0; i < 4; i++) {      // A tiles (hi, lo)
            int idx = tid + i * 256;       // 0..1023
            const __half* src = (idx < 512) ? Ahi : Alo;
            int within = idx & 511;
            int row = within >> 2, ck = within & 3;
            uint32_t dst = stBase + (idx >> 9) * A_TILE + row * SA_STRIDE + ck * 16;
            cp_async16(dst, src + (size_t)(mBase + row) * K + k0 + ck * 8);
        }
#pragma unroll
        for (int i = 0; i < 4; i++) {      // B tiles (hi, lo)
            int idx = tid + i * 256;
            const __half* src = (idx < 512) ? Whi : Wlo;
            int within = idx & 511;
            int row = within >> 4, ck = within & 15;
            uint32_t dst = stBase + 2 * A_TILE + (idx >> 9) * B_TILE + row * SB_STRIDE + ck * 16;
            cp_async16(dst, src + (size_t)(k0 + row) * N + nBase + ck * 8);
        }
        cp_commit();
    };

    load_stage(0, 0);
    if (nIter > 1) load_stage(1, 1);

    for (int it = 0; it < nIter; it++) {
        int stage = it % N_STAGE;
        if (it + 2 < nIter) { load_stage(it + 2, (it + 2) % N_STAGE); cp_wait<2>(); }
        else if (it + 1 < nIter) cp_wait<1>();
        else cp_wait<0>();
        __syncthreads();

        uint32_t stBase = sb + stage * STAGE_BYTES;
        uint32_t aHiB = stBase, aLoB = stBase + A_TILE;
        uint32_t bHiB = stBase + 2 * A_TILE, bLoB = bHiB + B_TILE;

#pragma unroll
        for (int ks = 0; ks < 2; ks++) {
            uint32_t ah[4][4], al[4][4], bh[4][2], bl[4][2];
#pragma unroll
            for (int mt = 0; mt < 4; mt++) {
                uint32_t off = (uint32_t)(wm * 64 + mt * 16 + (lid & 15)) * SA_STRIDE
                             + ks * 32 + (lid >> 4) * 16;
                ldsm_x4(ah[mt], aHiB + off);
                ldsm_x4(al[mt], aLoB + off);
            }
#pragma unroll
            for (int np = 0; np < 2; np++) {
                uint32_t off = (uint32_t)(ks * 16 + (lid & 15)) * SB_STRIDE
                             + (wn * 32 + np * 16 + (lid >> 4) * 8) * 2;
                uint32_t t[4];
                ldsm_x4_t(t, bHiB + off);
                bh[np*2][0] = t[0]; bh[np*2][1] = t[1];
                bh[np*2+1][0] = t[2]; bh[np*2+1][1] = t[3];
                ldsm_x4_t(t, bLoB + off);
                bl[np*2][0] = t[0]; bl[np*2][1] = t[1];
                bl[np*2+1][0] = t[2]; bl[np*2+1][1] = t[3];
            }
#pragma unroll
            for (int mt = 0; mt < 4; mt++)
#pragma unroll
                for (int nt = 0; nt < 4; nt++) {
                    mma16816(acc[mt][nt], ah[mt], bh[nt]);
                    mma16816(acc[mt][nt], ah[mt], bl[nt]);
                    mma16816(acc[mt][nt], al[mt], bh[nt]);
                }
        }
        __syncthreads();
    }

    // ---- epilogue ----
    int g = lid >> 2, ti = lid & 3;
#pragma unroll
    for (int mt = 0; mt < 4; mt++) {
        int m0 = mBase + wm * 64 + mt * 16 + g;
#pragma unroll
        for (int nt = 0; nt < 4; nt++) {
            int n0 = nBase + wn * 32 + nt * 8 + ti * 2;
            float b0 = bias[n0], b1 = bias[n0 + 1];
            float2 v0 = make_float2(acc[mt][nt][0] + b0, acc[mt][nt][1] + b1);
            float2 v1 = make_float2(acc[mt][nt][2] + b0, acc[mt][nt][3] + b1);
            *(float2*)(Cc + (size_t)m0 * N + n0) = v0;
            *(float2*)(Cc + (size_t)(m0 + 8) * N + n0) = v1;
        }
    }
}

// ======================= BatchNorm =======================
__global__ void bn_stats(const float* __restrict__ Y, float* __restrict__ mu,
                         float* __restrict__ var) {
    int c0 = blockIdx.x * 32;
    int tid = threadIdx.x;
    int c = tid % 32, r0 = tid / 32;
    float s = 0.f, s2 = 0.f;
    for (int r = r0; r < M_TOT; r += 8) {
        float v = Y[(size_t)r * FC + c0 + c];
        s += v; s2 += v * v;
    }
    __shared__ float sh[2][8][32];
    sh[0][r0][c] = s; sh[1][r0][c] = s2;
    __syncthreads();
    if (r0 == 0) {
        float ts = 0.f, ts2 = 0.f;
#pragma unroll
        for (int i = 0; i < 8; i++) { ts += sh[0][i][c]; ts2 += sh[1][i][c]; }
        float m = ts / (float)M_TOT;
        mu [c0 + c] = m;
        var[c0 + c] = ts2 / (float)M_TOT - m * m;
    }
}

__global__ void bn_apply_relu_split(const float* __restrict__ Y,
                                    const float* __restrict__ mu, const float* __restrict__ var,
                                    const float* __restrict__ g, const float* __restrict__ b,
                                    __half* __restrict__ hi, __half* __restrict__ lo) {
    int idx = blockIdx.x * blockDim.x + threadIdx.x;
    if (idx >= M_TOT * FC) return;
    int c = idx & (FC - 1);
    float v = Y[idx];
    v = (v - mu[c]) * rsqrtf(var[c] + 1e-5f) * g[c] + b[c];
    v = fmaxf(v, 0.f);
    __half h = __float2half_rn(v);
    hi[idx] = h;
    lo[idx] = __float2half_rn(v - __half2float(h));
}

__global__ void bn_apply_relu(float* __restrict__ Y, const float* __restrict__ mu,
                              const float* __restrict__ var,
                              const float* __restrict__ g, const float* __restrict__ b) {
    int idx = blockIdx.x * blockDim.x + threadIdx.x;
    if (idx >= M_TOT * FC) return;
    int c = idx & (FC - 1);
    float v = Y[idx];
    v = (v - mu[c]) * rsqrtf(var[c] + 1e-5f) * g[c] + b[c];
    Y[idx] = fmaxf(v, 0.f);
}

// ======================= heads =======================
__global__ void heads_kernel(const float* __restrict__ Y,
                             const float* __restrict__ cw,  const float* __restrict__ cb,
                             const float* __restrict__ bw,  const float* __restrict__ bb_,
                             const float* __restrict__ ycw, const float* __restrict__ ycb,
                             const float* __restrict__ yrw, const float* __restrict__ yrb,
                             const float* __restrict__ hw,  const float* __restrict__ hb,
                             float* __restrict__ out) {
    int row = blockIdx.x;
    __shared__ float sx[FC];
    int tid = threadIdx.x;
#pragma unroll
    for (int i = 0; i < FC / 128; i++)
        sx[tid + i * 128] = Y[(size_t)row * FC + tid + i * 128];
    __syncthreads();
    if (tid < OUT_D) {
        const float* w; const float* bias; int wd, off;
        if (tid < 4)        { w = cw;  bias = cb;  wd = 4;  off = 0;  }
        else if (tid < 22)  { w = bw;  bias = bb_; wd = 18; off = 4;  }
        else if (tid < 58)  { w = ycw; bias = ycb; wd = 36; off = 22; }
        else if (tid < 94)  { w = yrw; bias = yrb; wd = 36; off = 58; }
        else                { w = hw;  bias = hb;  wd = 6;  off = 94; }
        int j = tid - off;
        float acc = bias[j];
#pragma unroll 4
        for (int k = 0; k < FC; k++) acc += sx[k] * w[k * wd + j];
        out[(size_t)row * OUT_D + tid] = acc;
    }
}

// ======================= launch =======================
extern "C" void kernel_launch(void* const* d_in, const int* in_sizes, int n_in,
                              void* d_out, int out_size) {
    const float* feat0    = (const float*)d_in[0];
    const float* feat1    = (const float*)d_in[1];
    const float* feat2    = (const float*)d_in[2];
    const float* bbox2d   = (const float*)d_in[3];
    const int*   anchor   = (const int*)  d_in[4];
    const float* fc1_w    = (const float*)d_in[5];
    const float* fc1_b    = (const float*)d_in[6];
    const float* bn1_g    = (const float*)d_in[7];
    const float* bn1_b    = (const float*)d_in[8];
    const float* fc2_w    = (const float*)d_in[9];
    const float* fc2_b    = (const float*)d_in[10];
    const float* bn2_g    = (const float*)d_in[11];
    const float* bn2_b    = (const float*)d_in[12];
    const float* cate_w   = (const float*)d_in[13];
    const float* cate_b   = (const float*)d_in[14];
    const float* bbox3d_w = (const float*)d_in[15];
    const float* bbox3d_b = (const float*)d_in[16];
    const float* yawc_w   = (const float*)d_in[17];
    const float* yawc_b   = (const float*)d_in[18];
    const float* yawr_w   = (const float*)d_in[19];
    const float* yawr_b   = (const float*)d_in[20];
    const float* hgt_w    = (const float*)d_in[21];
    const float* hgt_b    = (const float*)d_in[22];
    float* out = (float*)d_out;

    float *pf0, *pf1, *pf2, *pY1, *pY2, *pmu, *pvar;
    __half *pXhi, *pXlo, *pW1hi, *pW1lo, *pW2hi, *pW2lo, *pA2hi, *pA2lo;
    cudaGetSymbolAddress((void**)&pf0, g_f0);
    cudaGetSymbolAddress((void**)&pf1, g_f1);
    cudaGetSymbolAddress((void**)&pf2, g_f2);
    cudaGetSymbolAddress((void**)&pXhi, g_Xhi);
    cudaGetSymbolAddress((void**)&pXlo, g_Xlo);
    cudaGetSymbolAddress((void**)&pW1hi, g_W1hi);
    cudaGetSymbolAddress((void**)&pW1lo, g_W1lo);
    cudaGetSymbolAddress((void**)&pW2hi, g_W2hi);
    cudaGetSymbolAddress((void**)&pW2lo, g_W2lo);
    cudaGetSymbolAddress((void**)&pA2hi, g_A2hi);
    cudaGetSymbolAddress((void**)&pA2lo, g_A2lo);
    cudaGetSymbolAddress((void**)&pY1, g_Y1);
    cudaGetSymbolAddress((void**)&pY2, g_Y2);
    cudaGetSymbolAddress((void**)&pmu, g_mu);
    cudaGetSymbolAddress((void**)&pvar, g_var);

    cudaFuncSetAttribute(gemm_split_f16, cudaFuncAttributeMaxDynamicSharedMemorySize, GEMM_SMEM);

    dim3 tpb(32, 8);
    transpose_nchw_nhwc<<<dim3(128*128/32, C_CH/32, B_SZ), tpb>>>(feat0, pf0, 128*128);
    transpose_nchw_nhwc<<<dim3(64*64/32,   C_CH/32, B_SZ), tpb>>>(feat1, pf1, 64*64);
    transpose_nchw_nhwc<<<dim3(32*32/32,   C_CH/32, B_SZ), tpb>>>(feat2, pf2, 32*32);

    split_w<<<(K1*FC + 255)/256, 256>>>(fc1_w, pW1hi, pW1lo, K1*FC);
    split_w<<<(FC*FC + 255)/256, 256>>>(fc2_w, pW2hi, pW2lo, FC*FC);

    roi_align_kernel<<<M_TOT, C_CH>>>(bbox2d, anchor);

    // FC1 (K = 12544)
    gemm_split_f16<<<dim3(FC/128, M_TOT/128), 256, GEMM_SMEM>>>(
        pXhi, pXlo, pW1hi, pW1lo, fc1_b, pY1, FC, K1);
    bn_stats<<<FC/32, 256>>>(pY1, pmu, pvar);
    bn_apply_relu_split<<<(M_TOT*FC + 255)/256, 256>>>(pY1, pmu, pvar, bn1_g, bn1_b, pA2hi, pA2lo);

    // FC2 (K = 1024)
    gemm_split_f16<<<dim3(FC/128, M_TOT/128), 256, GEMM_SMEM>>>(
        pA2hi, pA2lo, pW2hi, pW2lo, fc2_b, pY2, FC, FC);
    bn_stats<<<FC/32, 256>>>(pY2, pmu, pvar);
    bn_apply_relu<<<(M_TOT*FC + 255)/256, 256>>>(pY2, pmu, pvar, bn2_g, bn2_b);

    heads_kernel<<<M_TOT, 128>>>(pY2, cate_w, cate_b, bbox3d_w, bbox3d_b,
                                 yawc_w, yawc_b, yawr_w, yawr_b, hgt_w, hgt_b, out);
}

// round 9
// speedup vs baseline: 1.4088x; 1.4088x over previous
#include <cuda_runtime.h>
#include <cuda_fp16.h>
#include <cstdint>
#include <math.h>

#define RES 7
#define SAMP 14
#define C_CH 256
#define B_SZ 4
#define N_ROI 512
#define M_TOT 2048
#define K1 12544
#define FC 1024
#define OUT_D 100

// ======================= scratch =======================
__device__ float g_f0[(size_t)B_SZ * 128 * 128 * C_CH];
__device__ float g_f1[(size_t)B_SZ * 64 * 64 * C_CH];
__device__ float g_f2[(size_t)B_SZ * 32 * 32 * C_CH];
__device__ __half g_Xh[(size_t)M_TOT * K1];
__device__ __half g_W1hi[(size_t)K1 * FC];   // [K][N] native layout
__device__ __half g_W1lo[(size_t)K1 * FC];
__device__ __half g_W2hi[(size_t)FC * FC];
__device__ __half g_W2lo[(size_t)FC * FC];
__device__ __half g_A2h[(size_t)M_TOT * FC];
__device__ float g_Y1[(size_t)M_TOT * FC];
__device__ float g_Y2[(size_t)M_TOT * FC];
__device__ float g_mu[FC];
__device__ float g_var[FC];

// ======================= small PTX helpers =======================
__device__ __forceinline__ uint32_t smem_u32(const void* p) {
    uint32_t a;
    asm("{ .reg .u64 t; cvta.to.shared.u64 t, %1; cvt.u32.u64 %0, t; }" : "=r"(a) : "l"(p));
    return a;
}
__device__ __forceinline__ void cp_async16(uint32_t dst, const void* src) {
    asm volatile("cp.async.cg.shared.global [%0], [%1], 16;" :: "r"(dst), "l"(src));
}
__device__ __forceinline__ void cp_commit() { asm volatile("cp.async.commit_group;"); }
template <int N> __device__ __forceinline__ void cp_wait() {
    asm volatile("cp.async.wait_group %0;" :: "n"(N));
}
__device__ __forceinline__ void ldsm_x4(uint32_t r[4], uint32_t addr) {
    asm volatile("ldmatrix.sync.aligned.m8n8.x4.shared.b16 {%0,%1,%2,%3}, [%4];"
                 : "=r"(r[0]), "=r"(r[1]), "=r"(r[2]), "=r"(r[3]) : "r"(addr));
}
__device__ __forceinline__ void ldsm_x4_t(uint32_t r[4], uint32_t addr) {
    asm volatile("ldmatrix.sync.aligned.m8n8.x4.trans.shared.b16 {%0,%1,%2,%3}, [%4];"
                 : "=r"(r[0]), "=r"(r[1]), "=r"(r[2]), "=r"(r[3]) : "r"(addr));
}
__device__ __forceinline__ void mma16816(float c[4], const uint32_t a[4], const uint32_t b[2]) {
    asm volatile("mma.sync.aligned.m16n8k16.row.col.f32.f16.f16.f32 "
                 "{%0,%1,%2,%3}, {%4,%5,%6,%7}, {%8,%9}, {%0,%1,%2,%3};"
                 : "+f"(c[0]), "+f"(c[1]), "+f"(c[2]), "+f"(c[3])
                 : "r"(a[0]), "r"(a[1]), "r"(a[2]), "r"(a[3]), "r"(b[0]), "r"(b[1]));
}

// ======================= NCHW -> NHWC =======================
__global__ void transpose_nchw_nhwc(const float* __restrict__ in,
                                    float* __restrict__ out, int HW) {
    __shared__ float tile[32][33];
    int b  = blockIdx.z;
    int s0 = blockIdx.x * 32;
    int c0 = blockIdx.y * 32;
    int tx = threadIdx.x, ty = threadIdx.y;
    const float* inb = in + (size_t)b * C_CH * HW;
    float* outb = out + (size_t)b * HW * C_CH;
#pragma unroll
    for (int i = 0; i < 32; i += 8)
        tile[ty + i][tx] = inb[(size_t)(c0 + ty + i) * HW + s0 + tx];
    __syncthreads();
#pragma unroll
    for (int i = 0; i < 32; i += 8)
        outb[(size_t)(s0 + ty + i) * C_CH + c0 + tx] = tile[tx][ty + i];
}

// ======================= W fp32 -> hi/lo fp16 (vectorized) =======================
__global__ void split_w4(const float4* __restrict__ in, __half2* __restrict__ hi,
                         __half2* __restrict__ lo, int total4) {
    int i = blockIdx.x * blockDim.x + threadIdx.x;
    if (i >= total4) return;
    float4 v = in[i];
    __half hx = __float2half_rn(v.x), hy = __float2half_rn(v.y);
    __half hz = __float2half_rn(v.z), hw = __float2half_rn(v.w);
    hi[2 * i]     = __halves2half2(hx, hy);
    hi[2 * i + 1] = __halves2half2(hz, hw);
    lo[2 * i]     = __halves2half2(__float2half_rn(v.x - __half2float(hx)),
                                   __float2half_rn(v.y - __half2float(hy)));
    lo[2 * i + 1] = __halves2half2(__float2half_rn(v.z - __half2float(hz)),
                                   __float2half_rn(v.w - __half2float(hw)));
}

// ======================= ROI align -> X fp16 =======================
__global__ void roi_align_kernel(const float* __restrict__ bbox2d,
                                 const int* __restrict__ anchor) {
    int roi = blockIdx.x;
    int b   = roi / N_ROI;
    int tid = threadIdx.x;

    __shared__ int   ax_p0[2][SAMP], ax_p1[2][SAMP];
    __shared__ float ax_l [2][SAMP], ax_v [2][SAMP];
    __shared__ int   soff[196][4];
    __shared__ float swt [196][4];

    int level = anchor[roi] / 3;
    float scale = (level == 0) ? 0.25f : (level == 1) ? 0.125f : 0.0625f;
    int   H     = (level == 0) ? 128   : (level == 1) ? 64     : 32;
    const float* F = (level == 0) ? g_f0 : (level == 1) ? g_f1 : g_f2;
    F += b * H * H * C_CH;

    if (tid < 2 * SAMP) {
        int axis = tid / SAMP;
        int j    = tid % SAMP;
        float cy = bbox2d[roi*4+0], cx = bbox2d[roi*4+1];
        float hh = bbox2d[roi*4+2], ww = bbox2d[roi*4+3];
        float lo_ = (axis == 0) ? (cy - 0.5f*hh) : (cx - 0.5f*ww);
        float hi_ = (axis == 0) ? (cy + 0.5f*hh) : (cx + 0.5f*ww);
        float start = lo_ * scale - 0.5f;
        float bs    = (hi_ - lo_) * scale / (float)RES;
        float g     = ((float)j + 0.5f) * 0.5f;
        float pos   = start + g * bs;
        float valid = (pos > -1.0f && pos < (float)H) ? 1.0f : 0.0f;
        float p  = fminf(fmaxf(pos, 0.0f), (float)(H - 1));
        int  p0  = (int)floorf(p);
        int  p1  = min(p0 + 1, H - 1);
        ax_p0[axis][j] = p0;  ax_p1[axis][j] = p1;
        ax_l [axis][j] = p - (float)p0;
        ax_v [axis][j] = valid;
    }
    __syncthreads();

    if (tid < 196) {
        int j = tid / 14, i = tid % 14;
        int y0 = ax_p0[0][j], y1 = ax_p1[0][j];
        int x0 = ax_p0[1][i], x1 = ax_p1[1][i];
        float ly = ax_l[0][j], lx = ax_l[1][i];
        float hy = 1.f - ly,  hx = 1.f - lx;
        float wv = ax_v[0][j] * ax_v[1][i] * 0.25f;
        soff[tid][0] = (y0 * H + x0) * C_CH;  swt[tid][0] = hy * hx * wv;
        soff[tid][1] = (y0 * H + x1) * C_CH;  swt[tid][1] = hy * lx * wv;
        soff[tid][2] = (y1 * H + x0) * C_CH;  swt[tid][2] = ly * hx * wv;
        soff[tid][3] = (y1 * H + x1) * C_CH;  swt[tid][3] = ly * lx * wv;
    }
    __syncthreads();

    int c = tid;
    __half* xrow = g_Xh + (size_t)roi * K1 + c * 49;

#pragma unroll
    for (int py = 0; py < 7; py++) {
#pragma unroll
        for (int px = 0; px < 7; px++) {
            float v = 0.f;
#pragma unroll
            for (int sy = 0; sy < 2; sy++) {
#pragma unroll
                for (int sx = 0; sx < 2; sx++) {
                    int s = (py * 2 + sy) * 14 + px * 2 + sx;
#pragma unroll
                    for (int t = 0; t < 4; t++)
                        v += swt[s][t] * F[soff[s][t] + c];
                }
            }
            xrow[py * 7 + px] = __float2half_rn(v);
        }
    }
}

// ======================= fp16 2-pass HMMA GEMM =======================
// C[M,N] = A[M,K] @ (Whi+Wlo)[K,N] + bias, fp32 out.
// CTA 128x128, BK=32, 8 warps (2x4), warp tile 64x32, 4-stage cp.async.
#define SA_STRIDE 80               // 32 halves (64B) + 16B pad
#define SB_STRIDE 272              // 128 halves (256B) + 16B pad
#define A_TILE (128 * SA_STRIDE)   // 10240
#define B_TILE (32 * SB_STRIDE)    // 8704
#define STAGE_BYTES (A_TILE + 2 * B_TILE)   // 27648
#define N_STAGE 4
#define GEMM_SMEM (N_STAGE * STAGE_BYTES)   // 110592

__global__ void __launch_bounds__(256)
gemm_split_f16(const __half* __restrict__ A,
               const __half* __restrict__ Whi, const __half* __restrict__ Wlo,
               const float* __restrict__ bias, float* __restrict__ Cc,
               int N, int K) {
    extern __shared__ char smem[];
    uint32_t sb = smem_u32(smem);
    int tid = threadIdx.x, wid = tid >> 5, lid = tid & 31;
    int mBase = blockIdx.y * 128, nBase = blockIdx.x * 128;
    int wm = wid >> 2, wn = wid & 3;      // 2 x 4 warp grid

    float acc[4][4][4];
#pragma unroll
    for (int i = 0; i < 4; i++)
#pragma unroll
        for (int j = 0; j < 4; j++)
#pragma unroll
            for (int q = 0; q < 4; q++) acc[i][j][q] = 0.f;

    const int nIter = K >> 5;   // BK = 32

    auto load_stage = [&](int iter, int stage) {
        int k0 = iter * 32;
        uint32_t stBase = sb + stage * STAGE_BYTES;
        // A tile: 512 x 16B chunks, 2 per thread
#pragma unroll
        for (int i = 0; i < 2; i++) {
            int idx = tid + i * 256;       // 0..511
            int row = idx >> 2, ck = idx & 3;
            uint32_t dst = stBase + row * SA_STRIDE + ck * 16;
            cp_async16(dst, A + (size_t)(mBase + row) * K + k0 + ck * 8);
        }
        // B tiles (hi, lo): 1024 x 16B chunks, 4 per thread
#pragma unroll
        for (int i = 0; i < 4; i++) {
            int idx = tid + i * 256;
            const __half* src = (idx < 512) ? Whi : Wlo;
            int within = idx & 511;
            int row = within >> 4, ck = within & 15;
            uint32_t dst = stBase + A_TILE + (idx >> 9) * B_TILE + row * SB_STRIDE + ck * 16;
            cp_async16(dst, src + (size_t)(k0 + row) * N + nBase + ck * 8);
        }
        cp_commit();
    };

    load_stage(0, 0);
    if (nIter > 1) load_stage(1, 1);
    if (nIter > 2) load_stage(2, 2);

    for (int it = 0; it < nIter; it++) {
        int stage = it & 3;
        if (it + 3 < nIter) { load_stage(it + 3, (it + 3) & 3); cp_wait<3>(); }
        else if (it + 2 < nIter) cp_wait<2>();
        else if (it + 1 < nIter) cp_wait<1>();
        else cp_wait<0>();
        __syncthreads();

        uint32_t stBase = sb + stage * STAGE_BYTES;
        uint32_t aB = stBase;
        uint32_t bHiB = stBase + A_TILE, bLoB = bHiB + B_TILE;

#pragma unroll
        for (int ks = 0; ks < 2; ks++) {
            uint32_t ah[4][4], bh[4][2], bl[4][2];
#pragma unroll
            for (int mt = 0; mt < 4; mt++) {
                uint32_t off = (uint32_t)(wm * 64 + mt * 16 + (lid & 15)) * SA_STRIDE
                             + ks * 32 + (lid >> 4) * 16;
                ldsm_x4(ah[mt], aB + off);
            }
#pragma unroll
            for (int np = 0; np < 2; np++) {
                uint32_t off = (uint32_t)(ks * 16 + (lid & 15)) * SB_STRIDE
                             + (wn * 32 + np * 16 + (lid >> 4) * 8) * 2;
                uint32_t t[4];
                ldsm_x4_t(t, bHiB + off);
                bh[np*2][0] = t[0]; bh[np*2][1] = t[1];
                bh[np*2+1][0] = t[2]; bh[np*2+1][1] = t[3];
                ldsm_x4_t(t, bLoB + off);
                bl[np*2][0] = t[0]; bl[np*2][1] = t[1];
                bl[np*2+1][0] = t[2]; bl[np*2+1][1] = t[3];
            }
#pragma unroll
            for (int mt = 0; mt < 4; mt++)
#pragma unroll
                for (int nt = 0; nt < 4; nt++) {
                    mma16816(acc[mt][nt], ah[mt], bh[nt]);
                    mma16816(acc[mt][nt], ah[mt], bl[nt]);
                }
        }
        __syncthreads();
    }

    // ---- epilogue ----
    int g = lid >> 2, ti = lid & 3;
#pragma unroll
    for (int mt = 0; mt < 4; mt++) {
        int m0 = mBase + wm * 64 + mt * 16 + g;
#pragma unroll
        for (int nt = 0; nt < 4; nt++) {
            int n0 = nBase + wn * 32 + nt * 8 + ti * 2;
            float b0 = bias[n0], b1 = bias[n0 + 1];
            float2 v0 = make_float2(acc[mt][nt][0] + b0, acc[mt][nt][1] + b1);
            float2 v1 = make_float2(acc[mt][nt][2] + b0, acc[mt][nt][3] + b1);
            *(float2*)(Cc + (size_t)m0 * N + n0) = v0;
            *(float2*)(Cc + (size_t)(m0 + 8) * N + n0) = v1;
        }
    }
}

// ======================= BatchNorm =======================
__global__ void bn_stats(const float* __restrict__ Y, float* __restrict__ mu,
                         float* __restrict__ var) {
    int c0 = blockIdx.x * 32;
    int tid = threadIdx.x;
    int c = tid % 32, r0 = tid / 32;
    float s = 0.f, s2 = 0.f;
    for (int r = r0; r < M_TOT; r += 8) {
        float v = Y[(size_t)r * FC + c0 + c];
        s += v; s2 += v * v;
    }
    __shared__ float sh[2][8][32];
    sh[0][r0][c] = s; sh[1][r0][c] = s2;
    __syncthreads();
    if (r0 == 0) {
        float ts = 0.f, ts2 = 0.f;
#pragma unroll
        for (int i = 0; i < 8; i++) { ts += sh[0][i][c]; ts2 += sh[1][i][c]; }
        float m = ts / (float)M_TOT;
        mu [c0 + c] = m;
        var[c0 + c] = ts2 / (float)M_TOT - m * m;
    }
}

__global__ void bn_apply_relu_h(const float* __restrict__ Y,
                                const float* __restrict__ mu, const float* __restrict__ var,
                                const float* __restrict__ g, const float* __restrict__ b,
                                __half* __restrict__ out) {
    int idx = blockIdx.x * blockDim.x + threadIdx.x;
    if (idx >= M_TOT * FC) return;
    int c = idx & (FC - 1);
    float v = Y[idx];
    v = (v - mu[c]) * rsqrtf(var[c] + 1e-5f) * g[c] + b[c];
    out[idx] = __float2half_rn(fmaxf(v, 0.f));
}

__global__ void bn_apply_relu(float* __restrict__ Y, const float* __restrict__ mu,
                              const float* __restrict__ var,
                              const float* __restrict__ g, const float* __restrict__ b) {
    int idx = blockIdx.x * blockDim.x + threadIdx.x;
    if (idx >= M_TOT * FC) return;
    int c = idx & (FC - 1);
    float v = Y[idx];
    v = (v - mu[c]) * rsqrtf(var[c] + 1e-5f) * g[c] + b[c];
    Y[idx] = fmaxf(v, 0.f);
}

// ======================= heads =======================
__global__ void heads_kernel(const float* __restrict__ Y,
                             const float* __restrict__ cw,  const float* __restrict__ cb,
                             const float* __restrict__ bw,  const float* __restrict__ bb_,
                             const float* __restrict__ ycw, const float* __restrict__ ycb,
                             const float* __restrict__ yrw, const float* __restrict__ yrb,
                             const float* __restrict__ hw,  const float* __restrict__ hb,
                             float* __restrict__ out) {
    int row = blockIdx.x;
    __shared__ float sx[FC];
    int tid = threadIdx.x;
#pragma unroll
    for (int i = 0; i < FC / 128; i++)
        sx[tid + i * 128] = Y[(size_t)row * FC + tid + i * 128];
    __syncthreads();
    if (tid < OUT_D) {
        const float* w; const float* bias; int wd, off;
        if (tid < 4)        { w = cw;  bias = cb;  wd = 4;  off = 0;  }
        else if (tid < 22)  { w = bw;  bias = bb_; wd = 18; off = 4;  }
        else if (tid < 58)  { w = ycw; bias = ycb; wd = 36; off = 22; }
        else if (tid < 94)  { w = yrw; bias = yrb; wd = 36; off = 58; }
        else                { w = hw;  bias = hb;  wd = 6;  off = 94; }
        int j = tid - off;
        float acc = bias[j];
#pragma unroll 4
        for (int k = 0; k < FC; k++) acc += sx[k] * w[k * wd + j];
        out[(size_t)row * OUT_D + tid] = acc;
    }
}

// ======================= launch =======================
extern "C" void kernel_launch(void* const* d_in, const int* in_sizes, int n_in,
                              void* d_out, int out_size) {
    const float* feat0    = (const float*)d_in[0];
    const float* feat1    = (const float*)d_in[1];
    const float* feat2    = (const float*)d_in[2];
    const float* bbox2d   = (const float*)d_in[3];
    const int*   anchor   = (const int*)  d_in[4];
    const float* fc1_w    = (const float*)d_in[5];
    const float* fc1_b    = (const float*)d_in[6];
    const float* bn1_g    = (const float*)d_in[7];
    const float* bn1_b    = (const float*)d_in[8];
    const float* fc2_w    = (const float*)d_in[9];
    const float* fc2_b    = (const float*)d_in[10];
    const float* bn2_g    = (const float*)d_in[11];
    const float* bn2_b    = (const float*)d_in[12];
    const float* cate_w   = (const float*)d_in[13];
    const float* cate_b   = (const float*)d_in[14];
    const float* bbox3d_w = (const float*)d_in[15];
    const float* bbox3d_b = (const float*)d_in[16];
    const float* yawc_w   = (const float*)d_in[17];
    const float* yawc_b   = (const float*)d_in[18];
    const float* yawr_w   = (const float*)d_in[19];
    const float* yawr_b   = (const float*)d_in[20];
    const float* hgt_w    = (const float*)d_in[21];
    const float* hgt_b    = (const float*)d_in[22];
    float* out = (float*)d_out;

    float *pf0, *pf1, *pf2, *pY1, *pY2, *pmu, *pvar;
    __half *pXh, *pW1hi, *pW1lo, *pW2hi, *pW2lo, *pA2h;
    cudaGetSymbolAddress((void**)&pf0, g_f0);
    cudaGetSymbolAddress((void**)&pf1, g_f1);
    cudaGetSymbolAddress((void**)&pf2, g_f2);
    cudaGetSymbolAddress((void**)&pXh, g_Xh);
    cudaGetSymbolAddress((void**)&pW1hi, g_W1hi);
    cudaGetSymbolAddress((void**)&pW1lo, g_W1lo);
    cudaGetSymbolAddress((void**)&pW2hi, g_W2hi);
    cudaGetSymbolAddress((void**)&pW2lo, g_W2lo);
    cudaGetSymbolAddress((void**)&pA2h, g_A2h);
    cudaGetSymbolAddress((void**)&pY1, g_Y1);
    cudaGetSymbolAddress((void**)&pY2, g_Y2);
    cudaGetSymbolAddress((void**)&pmu, g_mu);
    cudaGetSymbolAddress((void**)&pvar, g_var);

    cudaFuncSetAttribute(gemm_split_f16, cudaFuncAttributeMaxDynamicSharedMemorySize, GEMM_SMEM);

    dim3 tpb(32, 8);
    transpose_nchw_nhwc<<<dim3(128*128/32, C_CH/32, B_SZ), tpb>>>(feat0, pf0, 128*128);
    transpose_nchw_nhwc<<<dim3(64*64/32,   C_CH/32, B_SZ), tpb>>>(feat1, pf1, 64*64);
    transpose_nchw_nhwc<<<dim3(32*32/32,   C_CH/32, B_SZ), tpb>>>(feat2, pf2, 32*32);

    split_w4<<<(K1*FC/4 + 255)/256, 256>>>((const float4*)fc1_w, (__half2*)pW1hi, (__half2*)pW1lo, K1*FC/4);
    split_w4<<<(FC*FC/4 + 255)/256, 256>>>((const float4*)fc2_w, (__half2*)pW2hi, (__half2*)pW2lo, FC*FC/4);

    roi_align_kernel<<<M_TOT, C_CH>>>(bbox2d, anchor);

    // FC1 (K = 12544)
    gemm_split_f16<<<dim3(FC/128, M_TOT/128), 256, GEMM_SMEM>>>(
        pXh, pW1hi, pW1lo, fc1_b, pY1, FC, K1);
    bn_stats<<<FC/32, 256>>>(pY1, pmu, pvar);
    bn_apply_relu_h<<<(M_TOT*FC + 255)/256, 256>>>(pY1, pmu, pvar, bn1_g, bn1_b, pA2h);

    // FC2 (K = 1024)
    gemm_split_f16<<<dim3(FC/128, M_TOT/128), 256, GEMM_SMEM>>>(
        pA2h, pW2hi, pW2lo, fc2_b, pY2, FC, FC);
    bn_stats<<<FC/32, 256>>>(pY2, pmu, pvar);
    bn_apply_relu<<<(M_TOT*FC + 255)/256, 256>>>(pY2, pmu, pvar, bn2_g, bn2_b);

    heads_kernel<<<M_TOT, 128>>>(pY2, cate_w, cate_b, bbox3d_w, bbox3d_b,
                                 yawc_w, yawc_b, yawr_w, yawr_b, hgt_w, hgt_b, out);
}

// round 10
// speedup vs baseline: 1.4154x; 1.0047x over previous
#include <cuda_runtime.h>
#include <cuda_fp16.h>
#include <cstdint>
#include <math.h>

#define RES 7
#define SAMP 14
#define C_CH 256
#define B_SZ 4
#define N_ROI 512
#define M_TOT 2048
#define K1 12544
#define FC 1024
#define OUT_D 100

// ======================= scratch =======================
__device__ float g_f0[(size_t)B_SZ * 128 * 128 * C_CH];
__device__ float g_f1[(size_t)B_SZ * 64 * 64 * C_CH];
__device__ float g_f2[(size_t)B_SZ * 32 * 32 * C_CH];
__device__ __half g_Xh[(size_t)M_TOT * K1];
__device__ __half g_W1hi[(size_t)K1 * FC];   // [K][N] native layout
__device__ __half g_W1lo[(size_t)K1 * FC];
__device__ __half g_W2hi[(size_t)FC * FC];
__device__ __half g_W2lo[(size_t)FC * FC];
__device__ __half g_A2h[(size_t)M_TOT * FC];
__device__ float g_Y1[(size_t)M_TOT * FC];
__device__ float g_Y2[(size_t)M_TOT * FC];
__device__ float g_mu[FC];
__device__ float g_var[FC];

// ======================= small PTX helpers =======================
__device__ __forceinline__ uint32_t smem_u32(const void* p) {
    uint32_t a;
    asm("{ .reg .u64 t; cvta.to.shared.u64 t, %1; cvt.u32.u64 %0, t; }" : "=r"(a) : "l"(p));
    return a;
}
__device__ __forceinline__ void cp_async16(uint32_t dst, const void* src) {
    asm volatile("cp.async.cg.shared.global [%0], [%1], 16;" :: "r"(dst), "l"(src));
}
__device__ __forceinline__ void cp_commit() { asm volatile("cp.async.commit_group;"); }
template <int N> __device__ __forceinline__ void cp_wait() {
    asm volatile("cp.async.wait_group %0;" :: "n"(N));
}
__device__ __forceinline__ void ldsm_x4(uint32_t r[4], uint32_t addr) {
    asm volatile("ldmatrix.sync.aligned.m8n8.x4.shared.b16 {%0,%1,%2,%3}, [%4];"
                 : "=r"(r[0]), "=r"(r[1]), "=r"(r[2]), "=r"(r[3]) : "r"(addr));
}
__device__ __forceinline__ void ldsm_x4_t(uint32_t r[4], uint32_t addr) {
    asm volatile("ldmatrix.sync.aligned.m8n8.x4.trans.shared.b16 {%0,%1,%2,%3}, [%4];"
                 : "=r"(r[0]), "=r"(r[1]), "=r"(r[2]), "=r"(r[3]) : "r"(addr));
}
__device__ __forceinline__ void mma16816(float c[4], const uint32_t a[4], const uint32_t b[2]) {
    asm volatile("mma.sync.aligned.m16n8k16.row.col.f32.f16.f16.f32 "
                 "{%0,%1,%2,%3}, {%4,%5,%6,%7}, {%8,%9}, {%0,%1,%2,%3};"
                 : "+f"(c[0]), "+f"(c[1]), "+f"(c[2]), "+f"(c[3])
                 : "r"(a[0]), "r"(a[1]), "r"(a[2]), "r"(a[3]), "r"(b[0]), "r"(b[1]));
}

// ======================= NCHW -> NHWC =======================
__global__ void transpose_nchw_nhwc(const float* __restrict__ in,
                                    float* __restrict__ out, int HW) {
    __shared__ float tile[32][33];
    int b  = blockIdx.z;
    int s0 = blockIdx.x * 32;
    int c0 = blockIdx.y * 32;
    int tx = threadIdx.x, ty = threadIdx.y;
    const float* inb = in + (size_t)b * C_CH * HW;
    float* outb = out + (size_t)b * HW * C_CH;
#pragma unroll
    for (int i = 0; i < 32; i += 8)
        tile[ty + i][tx] = inb[(size_t)(c0 + ty + i) * HW + s0 + tx];
    __syncthreads();
#pragma unroll
    for (int i = 0; i < 32; i += 8)
        outb[(size_t)(s0 + ty + i) * C_CH + c0 + tx] = tile[tx][ty + i];
}

// ======================= W fp32 -> hi/lo fp16 (vectorized) =======================
__global__ void split_w4(const float4* __restrict__ in, __half2* __restrict__ hi,
                         __half2* __restrict__ lo, int total4) {
    int i = blockIdx.x * blockDim.x + threadIdx.x;
    if (i >= total4) return;
    float4 v = in[i];
    __half hx = __float2half_rn(v.x), hy = __float2half_rn(v.y);
    __half hz = __float2half_rn(v.z), hw = __float2half_rn(v.w);
    hi[2 * i]     = __halves2half2(hx, hy);
    hi[2 * i + 1] = __halves2half2(hz, hw);
    lo[2 * i]     = __halves2half2(__float2half_rn(v.x - __half2float(hx)),
                                   __float2half_rn(v.y - __half2float(hy)));
    lo[2 * i + 1] = __halves2half2(__float2half_rn(v.z - __half2float(hz)),
                                   __float2half_rn(v.w - __half2float(hw)));
}

// ======================= ROI align -> X fp16 =======================
__global__ void roi_align_kernel(const float* __restrict__ bbox2d,
                                 const int* __restrict__ anchor) {
    int roi = blockIdx.x;
    int b   = roi / N_ROI;
    int tid = threadIdx.x;

    __shared__ int   ax_p0[2][SAMP], ax_p1[2][SAMP];
    __shared__ float ax_l [2][SAMP], ax_v [2][SAMP];
    __shared__ int   soff[196][4];
    __shared__ float swt [196][4];

    int level = anchor[roi] / 3;
    float scale = (level == 0) ? 0.25f : (level == 1) ? 0.125f : 0.0625f;
    int   H     = (level == 0) ? 128   : (level == 1) ? 64     : 32;
    const float* F = (level == 0) ? g_f0 : (level == 1) ? g_f1 : g_f2;
    F += b * H * H * C_CH;

    if (tid < 2 * SAMP) {
        int axis = tid / SAMP;
        int j    = tid % SAMP;
        float cy = bbox2d[roi*4+0], cx = bbox2d[roi*4+1];
        float hh = bbox2d[roi*4+2], ww = bbox2d[roi*4+3];
        float lo_ = (axis == 0) ? (cy - 0.5f*hh) : (cx - 0.5f*ww);
        float hi_ = (axis == 0) ? (cy + 0.5f*hh) : (cx + 0.5f*ww);
        float start = lo_ * scale - 0.5f;
        float bs    = (hi_ - lo_) * scale / (float)RES;
        float g     = ((float)j + 0.5f) * 0.5f;
        float pos   = start + g * bs;
        float valid = (pos > -1.0f && pos < (float)H) ? 1.0f : 0.0f;
        float p  = fminf(fmaxf(pos, 0.0f), (float)(H - 1));
        int  p0  = (int)floorf(p);
        int  p1  = min(p0 + 1, H - 1);
        ax_p0[axis][j] = p0;  ax_p1[axis][j] = p1;
        ax_l [axis][j] = p - (float)p0;
        ax_v [axis][j] = valid;
    }
    __syncthreads();

    if (tid < 196) {
        int j = tid / 14, i = tid % 14;
        int y0 = ax_p0[0][j], y1 = ax_p1[0][j];
        int x0 = ax_p0[1][i], x1 = ax_p1[1][i];
        float ly = ax_l[0][j], lx = ax_l[1][i];
        float hy = 1.f - ly,  hx = 1.f - lx;
        float wv = ax_v[0][j] * ax_v[1][i] * 0.25f;
        soff[tid][0] = (y0 * H + x0) * C_CH;  swt[tid][0] = hy * hx * wv;
        soff[tid][1] = (y0 * H + x1) * C_CH;  swt[tid][1] = hy * lx * wv;
        soff[tid][2] = (y1 * H + x0) * C_CH;  swt[tid][2] = ly * hx * wv;
        soff[tid][3] = (y1 * H + x1) * C_CH;  swt[tid][3] = ly * lx * wv;
    }
    __syncthreads();

    int c = tid;
    __half* xrow = g_Xh + (size_t)roi * K1 + c * 49;

#pragma unroll
    for (int py = 0; py < 7; py++) {
#pragma unroll
        for (int px = 0; px < 7; px++) {
            float v = 0.f;
#pragma unroll
            for (int sy = 0; sy < 2; sy++) {
#pragma unroll
                for (int sx = 0; sx < 2; sx++) {
                    int s = (py * 2 + sy) * 14 + px * 2 + sx;
#pragma unroll
                    for (int t = 0; t < 4; t++)
                        v += swt[s][t] * F[soff[s][t] + c];
                }
            }
            xrow[py * 7 + px] = __float2half_rn(v);
        }
    }
}

// ======================= fp16 2-pass HMMA GEMM =======================
// C[M,N] = A[M,K] @ (Whi+Wlo)[K,N] + bias, fp32 out.
// CTA 128x128, BK=32, 8 warps (2x4), warp tile 64x32, 4-stage cp.async.
#define SA_STRIDE 80               // 32 halves (64B) + 16B pad
#define SB_STRIDE 272              // 128 halves (256B) + 16B pad
#define A_TILE (128 * SA_STRIDE)   // 10240
#define B_TILE (32 * SB_STRIDE)    // 8704
#define STAGE_BYTES (A_TILE + 2 * B_TILE)   // 27648
#define N_STAGE 4
#define GEMM_SMEM (N_STAGE * STAGE_BYTES)   // 110592

__global__ void __launch_bounds__(256)
gemm_split_f16(const __half* __restrict__ A,
               const __half* __restrict__ Whi, const __half* __restrict__ Wlo,
               const float* __restrict__ bias, float* __restrict__ Cc,
               int N, int K) {
    extern __shared__ char smem[];
    uint32_t sb = smem_u32(smem);
    int tid = threadIdx.x, wid = tid >> 5, lid = tid & 31;
    int mBase = blockIdx.y * 128, nBase = blockIdx.x * 128;
    int wm = wid >> 2, wn = wid & 3;      // 2 x 4 warp grid

    float acc[4][4][4];
#pragma unroll
    for (int i = 0; i < 4; i++)
#pragma unroll
        for (int j = 0; j < 4; j++)
#pragma unroll
            for (int q = 0; q < 4; q++) acc[i][j][q] = 0.f;

    const int nIter = K >> 5;   // BK = 32

    auto load_stage = [&](int iter, int stage) {
        int k0 = iter * 32;
        uint32_t stBase = sb + stage * STAGE_BYTES;
        // A tile: 512 x 16B chunks, 2 per thread
#pragma unroll
        for (int i = 0; i < 2; i++) {
            int idx = tid + i * 256;       // 0..511
            int row = idx >> 2, ck = idx & 3;
            uint32_t dst = stBase + row * SA_STRIDE + ck * 16;
            cp_async16(dst, A + (size_t)(mBase + row) * K + k0 + ck * 8);
        }
        // B tiles (hi, lo): 1024 x 16B chunks, 4 per thread
#pragma unroll
        for (int i = 0; i < 4; i++) {
            int idx = tid + i * 256;
            const __half* src = (idx < 512) ? Whi : Wlo;
            int within = idx & 511;
            int row = within >> 4, ck = within & 15;
            uint32_t dst = stBase + A_TILE + (idx >> 9) * B_TILE + row * SB_STRIDE + ck * 16;
            cp_async16(dst, src + (size_t)(k0 + row) * N + nBase + ck * 8);
        }
        cp_commit();
    };

    load_stage(0, 0);
    if (nIter > 1) load_stage(1, 1);
    if (nIter > 2) load_stage(2, 2);

    for (int it = 0; it < nIter; it++) {
        int stage = it & 3;
        if (it + 3 < nIter) { load_stage(it + 3, (it + 3) & 3); cp_wait<3>(); }
        else if (it + 2 < nIter) cp_wait<2>();
        else if (it + 1 < nIter) cp_wait<1>();
        else cp_wait<0>();
        __syncthreads();

        uint32_t stBase = sb + stage * STAGE_BYTES;
        uint32_t aB = stBase;
        uint32_t bHiB = stBase + A_TILE, bLoB = bHiB + B_TILE;

#pragma unroll
        for (int ks = 0; ks < 2; ks++) {
            uint32_t ah[4][4], bh[4][2], bl[4][2];
#pragma unroll
            for (int mt = 0; mt < 4; mt++) {
                uint32_t off = (uint32_t)(wm * 64 + mt * 16 + (lid & 15)) * SA_STRIDE
                             + ks * 32 + (lid >> 4) * 16;
                ldsm_x4(ah[mt], aB + off);
            }
#pragma unroll
            for (int np = 0; np < 2; np++) {
                uint32_t off = (uint32_t)(ks * 16 + (lid & 15)) * SB_STRIDE
                             + (wn * 32 + np * 16 + (lid >> 4) * 8) * 2;
                uint32_t t[4];
                ldsm_x4_t(t, bHiB + off);
                bh[np*2][0] = t[0]; bh[np*2][1] = t[1];
                bh[np*2+1][0] = t[2]; bh[np*2+1][1] = t[3];
                ldsm_x4_t(t, bLoB + off);
                bl[np*2][0] = t[0]; bl[np*2][1] = t[1];
                bl[np*2+1][0] = t[2]; bl[np*2+1][1] = t[3];
            }
#pragma unroll
            for (int mt = 0; mt < 4; mt++)
#pragma unroll
                for (int nt = 0; nt < 4; nt++) {
                    mma16816(acc[mt][nt], ah[mt], bh[nt]);
                    mma16816(acc[mt][nt], ah[mt], bl[nt]);
                }
        }
        __syncthreads();
    }

    // ---- epilogue ----
    int g = lid >> 2, ti = lid & 3;
#pragma unroll
    for (int mt = 0; mt < 4; mt++) {
        int m0 = mBase + wm * 64 + mt * 16 + g;
#pragma unroll
        for (int nt = 0; nt < 4; nt++) {
            int n0 = nBase + wn * 32 + nt * 8 + ti * 2;
            float b0 = bias[n0], b1 = bias[n0 + 1];
            float2 v0 = make_float2(acc[mt][nt][0] + b0, acc[mt][nt][1] + b1);
            float2 v1 = make_float2(acc[mt][nt][2] + b0, acc[mt][nt][3] + b1);
            *(float2*)(Cc + (size_t)m0 * N + n0) = v0;
            *(float2*)(Cc + (size_t)(m0 + 8) * N + n0) = v1;
        }
    }
}

// ======================= BatchNorm =======================
__global__ void bn_stats(const float* __restrict__ Y, float* __restrict__ mu,
                         float* __restrict__ var) {
    int c0 = blockIdx.x * 32;
    int tid = threadIdx.x;
    int c = tid % 32, r0 = tid / 32;
    float s = 0.f, s2 = 0.f;
    for (int r = r0; r < M_TOT; r += 8) {
        float v = Y[(size_t)r * FC + c0 + c];
        s += v; s2 += v * v;
    }
    __shared__ float sh[2][8][32];
    sh[0][r0][c] = s; sh[1][r0][c] = s2;
    __syncthreads();
    if (r0 == 0) {
        float ts = 0.f, ts2 = 0.f;
#pragma unroll
        for (int i = 0; i < 8; i++) { ts += sh[0][i][c]; ts2 += sh[1][i][c]; }
        float m = ts / (float)M_TOT;
        mu [c0 + c] = m;
        var[c0 + c] = ts2 / (float)M_TOT - m * m;
    }
}

__global__ void bn_apply_relu_h(const float* __restrict__ Y,
                                const float* __restrict__ mu, const float* __restrict__ var,
                                const float* __restrict__ g, const float* __restrict__ b,
                                __half* __restrict__ out) {
    int idx = blockIdx.x * blockDim.x + threadIdx.x;
    if (idx >= M_TOT * FC) return;
    int c = idx & (FC - 1);
    float v = Y[idx];
    v = (v - mu[c]) * rsqrtf(var[c] + 1e-5f) * g[c] + b[c];
    out[idx] = __float2half_rn(fmaxf(v, 0.f));
}

__global__ void bn_apply_relu(float* __restrict__ Y, const float* __restrict__ mu,
                              const float* __restrict__ var,
                              const float* __restrict__ g, const float* __restrict__ b) {
    int idx = blockIdx.x * blockDim.x + threadIdx.x;
    if (idx >= M_TOT * FC) return;
    int c = idx & (FC - 1);
    float v = Y[idx];
    v = (v - mu[c]) * rsqrtf(var[c] + 1e-5f) * g[c] + b[c];
    Y[idx] = fmaxf(v, 0.f);
}

// ======================= heads =======================
__global__ void heads_kernel(const float* __restrict__ Y,
                             const float* __restrict__ cw,  const float* __restrict__ cb,
                             const float* __restrict__ bw,  const float* __restrict__ bb_,
                             const float* __restrict__ ycw, const float* __restrict__ ycb,
                             const float* __restrict__ yrw, const float* __restrict__ yrb,
                             const float* __restrict__ hw,  const float* __restrict__ hb,
                             float* __restrict__ out) {
    int row = blockIdx.x;
    __shared__ float sx[FC];
    int tid = threadIdx.x;
#pragma unroll
    for (int i = 0; i < FC / 128; i++)
        sx[tid + i * 128] = Y[(size_t)row * FC + tid + i * 128];
    __syncthreads();
    if (tid < OUT_D) {
        const float* w; const float* bias; int wd, off;
        if (tid < 4)        { w = cw;  bias = cb;  wd = 4;  off = 0;  }
        else if (tid < 22)  { w = bw;  bias = bb_; wd = 18; off = 4;  }
        else if (tid < 58)  { w = ycw; bias = ycb; wd = 36; off = 22; }
        else if (tid < 94)  { w = yrw; bias = yrb; wd = 36; off = 58; }
        else                { w = hw;  bias = hb;  wd = 6;  off = 94; }
        int j = tid - off;
        float acc = bias[j];
#pragma unroll 4
        for (int k = 0; k < FC; k++) acc += sx[k] * w[k * wd + j];
        out[(size_t)row * OUT_D + tid] = acc;
    }
}

// ======================= launch =======================
extern "C" void kernel_launch(void* const* d_in, const int* in_sizes, int n_in,
                              void* d_out, int out_size) {
    const float* feat0    = (const float*)d_in[0];
    const float* feat1    = (const float*)d_in[1];
    const float* feat2    = (const float*)d_in[2];
    const float* bbox2d   = (const float*)d_in[3];
    const int*   anchor   = (const int*)  d_in[4];
    const float* fc1_w    = (const float*)d_in[5];
    const float* fc1_b    = (const float*)d_in[6];
    const float* bn1_g    = (const float*)d_in[7];
    const float* bn1_b    = (const float*)d_in[8];
    const float* fc2_w    = (const float*)d_in[9];
    const float* fc2_b    = (const float*)d_in[10];
    const float* bn2_g    = (const float*)d_in[11];
    const float* bn2_b    = (const float*)d_in[12];
    const float* cate_w   = (const float*)d_in[13];
    const float* cate_b   = (const float*)d_in[14];
    const float* bbox3d_w = (const float*)d_in[15];
    const float* bbox3d_b = (const float*)d_in[16];
    const float* yawc_w   = (const float*)d_in[17];
    const float* yawc_b   = (const float*)d_in[18];
    const float* yawr_w   = (const float*)d_in[19];
    const float* yawr_b   = (const float*)d_in[20];
    const float* hgt_w    = (const float*)d_in[21];
    const float* hgt_b    = (const float*)d_in[22];
    float* out = (float*)d_out;

    float *pf0, *pf1, *pf2, *pY1, *pY2, *pmu, *pvar;
    __half *pXh, *pW1hi, *pW1lo, *pW2hi, *pW2lo, *pA2h;
    cudaGetSymbolAddress((void**)&pf0, g_f0);
    cudaGetSymbolAddress((void**)&pf1, g_f1);
    cudaGetSymbolAddress((void**)&pf2, g_f2);
    cudaGetSymbolAddress((void**)&pXh, g_Xh);
    cudaGetSymbolAddress((void**)&pW1hi, g_W1hi);
    cudaGetSymbolAddress((void**)&pW1lo, g_W1lo);
    cudaGetSymbolAddress((void**)&pW2hi, g_W2hi);
    cudaGetSymbolAddress((void**)&pW2lo, g_W2lo);
    cudaGetSymbolAddress((void**)&pA2h, g_A2h);
    cudaGetSymbolAddress((void**)&pY1, g_Y1);
    cudaGetSymbolAddress((void**)&pY2, g_Y2);
    cudaGetSymbolAddress((void**)&pmu, g_mu);
    cudaGetSymbolAddress((void**)&pvar, g_var);

    cudaFuncSetAttribute(gemm_split_f16, cudaFuncAttributeMaxDynamicSharedMemorySize, GEMM_SMEM);

    dim3 tpb(32, 8);
    transpose_nchw_nhwc<<<dim3(128*128/32, C_CH/32, B_SZ), tpb>>>(feat0, pf0, 128*128);
    transpose_nchw_nhwc<<<dim3(64*64/32,   C_CH/32, B_SZ), tpb>>>(feat1, pf1, 64*64);
    transpose_nchw_nhwc<<<dim3(32*32/32,   C_CH/32, B_SZ), tpb>>>(feat2, pf2, 32*32);

    split_w4<<<(K1*FC/4 + 255)/256, 256>>>((const float4*)fc1_w, (__half2*)pW1hi, (__half2*)pW1lo, K1*FC/4);
    split_w4<<<(FC*FC/4 + 255)/256, 256>>>((const float4*)fc2_w, (__half2*)pW2hi, (__half2*)pW2lo, FC*FC/4);

    roi_align_kernel<<<M_TOT, C_CH>>>(bbox2d, anchor);

    // FC1 (K = 12544)
    gemm_split_f16<<<dim3(FC/128, M_TOT/128), 256, GEMM_SMEM>>>(
        pXh, pW1hi, pW1lo, fc1_b, pY1, FC, K1);
    bn_stats<<<FC/32, 256>>>(pY1, pmu, pvar);
    bn_apply_relu_h<<<(M_TOT*FC + 255)/256, 256>>>(pY1, pmu, pvar, bn1_g, bn1_b, pA2h);

    // FC2 (K = 1024)
    gemm_split_f16<<<dim3(FC/128, M_TOT/128), 256, GEMM_SMEM>>>(
        pA2h, pW2hi, pW2lo, fc2_b, pY2, FC, FC);
    bn_stats<<<FC/32, 256>>>(pY2, pmu, pvar);
    bn_apply_relu<<<(M_TOT*FC + 255)/256, 256>>>(pY2, pmu, pvar, bn2_g, bn2_b);

    heads_kernel<<<M_TOT, 128>>>(pY2, cate_w, cate_b, bbox3d_w, bbox3d_b,
                                 yawc_w, yawc_b, yawr_w, yawr_b, hgt_w, hgt_b, out);
}